// round 7
// baseline (speedup 1.0000x reference)
#include <cuda_runtime.h>
#include <cuda_fp16.h>
#include <cstdint>
#include <math.h>

#define NHALF 4096
#define NROWS 8192
#define D 256
#define TILE 128
#define NTG 64                 // 64x64 tile grid

// ---------------- device globals (no allocs allowed) ----------------
__device__ __align__(16) float  g_zn[NROWS * D];   // fp32 rows (pos dot)
__device__ __align__(16) __half g_zh[NROWS * D];   // fp16 rows (MMA)
__device__ float g_denom[NROWS];
__device__ float g_acc[2];

// ---------------- PTX helpers (arch-portable sm_80+ forms only) ----------
__device__ __forceinline__ uint32_t smem_u32(const void* p) {
    uint32_t a;
    asm("{ .reg .u64 t; cvta.to.shared.u64 t, %1; cvt.u32.u64 %0, t; }" : "=r"(a) : "l"(p));
    return a;
}
#define CPASYNC16(dst, src) \
    asm volatile("cp.async.cg.shared.global [%0], [%1], 16;" :: "r"(dst), "l"(src))
#define CPCOMMIT() asm volatile("cp.async.commit_group;" ::: "memory")
#define CPWAIT(n)  asm volatile("cp.async.wait_group %0;" :: "n"(n) : "memory")

#define LDSM4(r0, r1, r2, r3, a) \
    asm volatile("ldmatrix.sync.aligned.m8n8.x4.shared.b16 {%0,%1,%2,%3},[%4];" \
        : "=r"(r0), "=r"(r1), "=r"(r2), "=r"(r3) : "r"(a))

#define MMA16816(d, a, b) \
    asm volatile("mma.sync.aligned.m16n8k16.row.col.f32.f16.f16.f32 " \
        "{%0,%1,%2,%3},{%4,%5,%6,%7},{%8,%9},{%0,%1,%2,%3};" \
        : "+f"((d)[0]), "+f"((d)[1]), "+f"((d)[2]), "+f"((d)[3]) \
        : "r"((a)[0]), "r"((a)[1]), "r"((a)[2]), "r"((a)[3]), "r"((b)[0]), "r"((b)[1]))

__device__ __forceinline__ float ex2f(float x) {
    float y;
    asm("ex2.approx.f32 %0, %1;" : "=f"(y) : "f"(x));
    return y;
}

// ---------------------------------------------------------------------------
// K1: normalize rows of concat(z_i,z_j): fp32 + fp16 copies; zero accumulators.
// ---------------------------------------------------------------------------
__global__ void k_normalize(const float* __restrict__ z_i,
                            const float* __restrict__ z_j) {
    int row = blockIdx.x;
    int t = threadIdx.x;
    const float* src = (row < NHALF) ? (z_i + (size_t)row * D)
                                     : (z_j + (size_t)(row - NHALF) * D);
    float v = src[t];
    float ss = v * v;
#pragma unroll
    for (int o = 16; o; o >>= 1) ss += __shfl_xor_sync(0xffffffffu, ss, o);
    __shared__ float sh[8];
    if ((t & 31) == 0) sh[t >> 5] = ss;
    __syncthreads();
    float tot = 0.f;
#pragma unroll
    for (int i = 0; i < 8; i++) tot += sh[i];
    float norm = fmaxf(sqrtf(tot), 1e-8f);
    float zn = v / norm;
    g_zn[(size_t)row * D + t] = zn;
    g_zh[(size_t)row * D + t] = __float2half(zn);
    if (t == 0) {
        g_denom[row] = 0.f;
        if (row == 0) { g_acc[0] = 0.f; g_acc[1] = 0.f; }
    }
}

// ---------------------------------------------------------------------------
// Async-copy one 128x256 fp16 tile into XOR-swizzled SMEM.
// ---------------------------------------------------------------------------
__device__ __forceinline__ void load_tile_async(uint32_t sdst, const char* gsrc, int tid) {
#pragma unroll
    for (int i = 0; i < 16; i++) {
        int c = tid + i * 256;            // 0..4095 16B chunks
        int r = c >> 5, cc = c & 31;
        uint32_t dst = sdst + r * 512 + ((cc ^ (r & 7)) << 4);
        CPASYNC16(dst, gsrc + (size_t)c * 16);
    }
}

// SMEM layout for k_sim
#define SM_B0    65536
#define SM_B1    131072
#define SM_COL   196608                  // 128-float col accumulator
#define SM_RED   (196608 + 512)         // 128-float row-reduce buffer
#define SM_TOTAL (196608 + 1024)

// ---------------------------------------------------------------------------
// K2: symmetric-half HMMA sim GEMM. Only tiles tj >= ti are computed; each
// off-diagonal tile feeds row-sums (regs->atomics) AND col-sums (smem->atomics).
// Pair schedule: pair p = {tile-row p, tile-row 63-p} = 65 tiles, split over
// 4 CTAs (stride 4) -> 128 CTAs x 16-17 tiles, A resident per segment.
// ---------------------------------------------------------------------------
__global__ void __launch_bounds__(256) k_sim() {
    extern __shared__ char smem[];
    const int tid = threadIdx.x;
    const int wid = tid >> 5, lane = tid & 31;
    const int p = blockIdx.x >> 2, q = blockIdx.x & 3;
    const int nA = NTG - p;              // tiles in first segment (row p)
    const int warp_row = (wid & 3) * 32;
    const int warp_col = (wid >> 2) * 64;

    const uint32_t sbA = smem_u32(smem);
    const uint32_t sbB[2] = { sbA + SM_B0, sbA + SM_B1 };
    float* colbuf = (float*)(smem + SM_COL);
    float* sred   = (float*)(smem + SM_RED);

    if (tid < 128) colbuf[tid] = 0.f;

    // tile-list decode: global list index m -> (ti, tj)
    auto decode = [&](int m, int& ti_, int& tj_) {
        if (m < nA) { ti_ = p; tj_ = p + m; }
        else        { ti_ = NTG - 1 - p; tj_ = (NTG - 1 - p) + (m - nA); }
    };

    int ti, tj;
    decode(q, ti, tj);

    // initial loads: A(ti) + B(tj)
    load_tile_async(sbA, (const char*)(g_zh + (size_t)ti * TILE * D), tid);
    load_tile_async(sbB[0], (const char*)(g_zh + (size_t)tj * TILE * D), tid);
    CPCOMMIT(); CPWAIT(0);
    __syncthreads();

    // ldmatrix address precompute
    uint32_t baseA[2]; int swA[2];
    const int hiA = lane >> 4;
#pragma unroll
    for (int mi = 0; mi < 2; mi++) {
        int rA = warp_row + mi * 16 + (lane & 15);
        baseA[mi] = sbA + rA * 512;
        swA[mi] = rA & 7;
    }
    uint32_t relB[4]; int swB[4];
    const int hiB = (lane >> 3) & 1;
#pragma unroll
    for (int np = 0; np < 4; np++) {
        int nB = warp_col + np * 16 + (lane & 7) + ((lane & 16) >> 1);
        relB[np] = nB * 512;
        swB[np] = nB & 7;
    }

    const int lr0 = warp_row + (lane >> 2);      // local row of acc[...][0]
    const int lc0 = warp_col + 2 * (lane & 3);   // local col of elt 0
    const float K2E = 2.8853900817779268f;       // exp(2s) = 2^(s*K2E)

    float rsum[2][2] = {{0.f, 0.f}, {0.f, 0.f}};

    // row-sum flush for current tile-row ti (atomics; rsum reset by caller)
    auto flush_rows = [&](int tiF) {
        __syncthreads();
#pragma unroll
        for (int mi = 0; mi < 2; mi++)
#pragma unroll
            for (int h = 0; h < 2; h++) {
                float v = rsum[mi][h];
                v += __shfl_xor_sync(0xffffffffu, v, 1);
                v += __shfl_xor_sync(0xffffffffu, v, 2);
                if ((lane & 3) == 0 && (wid >> 2) == 1)
                    sred[warp_row + mi * 16 + h * 8 + (lane >> 2)] = v;
                rsum[mi][h] = v;
            }
        __syncthreads();
        if ((wid >> 2) == 0 && (lane & 3) == 0) {
#pragma unroll
            for (int mi = 0; mi < 2; mi++)
#pragma unroll
                for (int h = 0; h < 2; h++) {
                    int lr = warp_row + mi * 16 + h * 8 + (lane >> 2);
                    atomicAdd(&g_denom[tiF * TILE + lr], rsum[mi][h] + sred[lr]);
                }
        }
        rsum[0][0] = rsum[0][1] = rsum[1][0] = rsum[1][1] = 0.f;
    };

#pragma unroll 1
    for (int n = 0; ; n++) {
        const int m = q + 4 * n;
        const int mn = m + 4;
        const bool hasNext = (mn < NTG + 1);
        int ti2 = 0, tj2 = 0;
        if (hasNext) decode(mn, ti2, tj2);
        const bool sameRow = hasNext && (ti2 == ti);

        // prefetch next B if staying on this tile-row (buffer n-1 is free)
        if (sameRow) {
            load_tile_async(sbB[(n + 1) & 1],
                            (const char*)(g_zh + (size_t)tj2 * TILE * D), tid);
            CPCOMMIT();
        }

        // ---- mainloop: fp32-acc HMMA over K=256 ----
        const uint32_t sbBt = sbB[n & 1];
        float acc[2][8][4];
#pragma unroll
        for (int mi = 0; mi < 2; mi++)
#pragma unroll
            for (int ni = 0; ni < 8; ni++)
#pragma unroll
                for (int c = 0; c < 4; c++) acc[mi][ni][c] = 0.f;

#pragma unroll
        for (int s = 0; s < 16; s++) {
            uint32_t af[2][4];
#pragma unroll
            for (int mi = 0; mi < 2; mi++)
                LDSM4(af[mi][0], af[mi][1], af[mi][2], af[mi][3],
                      baseA[mi] + (((2 * s + hiA) ^ swA[mi]) << 4));
            uint32_t bfr[8][2];
#pragma unroll
            for (int np = 0; np < 4; np++) {
                uint32_t t0, t1, t2, t3;
                LDSM4(t0, t1, t2, t3,
                      sbBt + relB[np] + (((2 * s + hiB) ^ swB[np]) << 4));
                bfr[2 * np][0] = t0;     bfr[2 * np][1] = t1;
                bfr[2 * np + 1][0] = t2; bfr[2 * np + 1][1] = t3;
            }
#pragma unroll
            for (int mi = 0; mi < 2; mi++)
#pragma unroll
                for (int ni = 0; ni < 8; ni++)
                    MMA16816(acc[mi][ni], af[mi], bfr[ni]);
        }

        // ---- epilogue: exps, row-sums (regs), col-sums (smem) ----
        const bool diag = (ti == tj);
        float cs[8][2];
#pragma unroll
        for (int ni = 0; ni < 8; ni++) { cs[ni][0] = 0.f; cs[ni][1] = 0.f; }

#pragma unroll
        for (int mi = 0; mi < 2; mi++) {
#pragma unroll
            for (int ni = 0; ni < 8; ni++) {
                float e0 = ex2f(acc[mi][ni][0] * K2E);
                float e1 = ex2f(acc[mi][ni][1] * K2E);
                float e2 = ex2f(acc[mi][ni][2] * K2E);
                float e3 = ex2f(acc[mi][ni][3] * K2E);
                if (diag) {
                    int gr = lr0 + mi * 16;
                    int gc = lc0 + ni * 8;
                    if (gc == gr) e0 = 0.f;
                    if (gc + 1 == gr) e1 = 0.f;
                    if (gc == gr + 8) e2 = 0.f;
                    if (gc + 1 == gr + 8) e3 = 0.f;
                }
                rsum[mi][0] += e0 + e1;
                rsum[mi][1] += e2 + e3;
                cs[ni][0] += e0 + e2;    // col lc0 + ni*8
                cs[ni][1] += e1 + e3;    // col lc0 + ni*8 + 1
            }
        }

        if (!diag) {
            // reduce col partials across the 8 lane row-groups
#pragma unroll
            for (int ni = 0; ni < 8; ni++)
#pragma unroll
                for (int h = 0; h < 2; h++) {
                    float v = cs[ni][h];
                    v += __shfl_xor_sync(0xffffffffu, v, 4);
                    v += __shfl_xor_sync(0xffffffffu, v, 8);
                    v += __shfl_xor_sync(0xffffffffu, v, 16);
                    cs[ni][h] = v;
                }
            // lane group g = lane>>2 writes ni == g (64 distinct cols per warp)
            int g = lane >> 2;
            int cidx = warp_col + g * 8 + 2 * (lane & 3);
            float v0, v1;
            switch (g) {     // static indexing of cs
                case 0: v0 = cs[0][0]; v1 = cs[0][1]; break;
                case 1: v0 = cs[1][0]; v1 = cs[1][1]; break;
                case 2: v0 = cs[2][0]; v1 = cs[2][1]; break;
                case 3: v0 = cs[3][0]; v1 = cs[3][1]; break;
                case 4: v0 = cs[4][0]; v1 = cs[4][1]; break;
                case 5: v0 = cs[5][0]; v1 = cs[5][1]; break;
                case 6: v0 = cs[6][0]; v1 = cs[6][1]; break;
                default: v0 = cs[7][0]; v1 = cs[7][1]; break;
            }
            atomicAdd(&colbuf[cidx], v0);
            atomicAdd(&colbuf[cidx + 1], v1);
        }
        __syncthreads();
        if (!diag && tid < 128) {
            float v = colbuf[tid];
            colbuf[tid] = 0.f;
            atomicAdd(&g_denom[tj * TILE + tid], v);
        }

        if (!hasNext) break;
        if (sameRow) {
            CPWAIT(0);
            __syncthreads();
            tj = tj2;
        } else {
            // segment switch: flush row-sums, reload A + first B of new row
            flush_rows(ti);
            __syncthreads();
            load_tile_async(sbA, (const char*)(g_zh + (size_t)ti2 * TILE * D), tid);
            load_tile_async(sbB[(n + 1) & 1],
                            (const char*)(g_zh + (size_t)tj2 * TILE * D), tid);
            CPCOMMIT(); CPWAIT(0);
            __syncthreads();
            ti = ti2; tj = tj2;
        }
    }

    flush_rows(ti);
}

// ---------------------------------------------------------------------------
// K3: fused positives + weighted loss. One warp per pair i (fp32 dot).
// ---------------------------------------------------------------------------
__global__ void k_loss(const float* __restrict__ w) {
    int gw = (blockIdx.x * blockDim.x + threadIdx.x) >> 5;   // pair id 0..4095
    int lane = threadIdx.x & 31;
    const float4* a = (const float4*)(g_zn + (size_t)gw * D);
    const float4* b = (const float4*)(g_zn + (size_t)(gw + NHALF) * D);
    float s = 0.f;
#pragma unroll
    for (int p = 0; p < 2; p++) {
        float4 x = a[lane + p * 32];
        float4 y = b[lane + p * 32];
        s += x.x * y.x + x.y * y.y + x.z * y.z + x.w * y.w;
    }
#pragma unroll
    for (int o = 16; o; o >>= 1) s += __shfl_xor_sync(0xffffffffu, s, o);

    __shared__ float s_num[8], s_den[8];
    int wrp = threadIdx.x >> 5;
    if (lane == 0) {
        float wi = w[gw];
        s_num[wrp] = wi * (logf(g_denom[gw]) + logf(g_denom[gw + NHALF]) - 4.0f * s);
        s_den[wrp] = 2.0f * wi;
    }
    __syncthreads();
    if (threadIdx.x == 0) {
        float n = 0.f, d = 0.f;
#pragma unroll
        for (int j = 0; j < 8; j++) { n += s_num[j]; d += s_den[j]; }
        atomicAdd(&g_acc[0], n);
        atomicAdd(&g_acc[1], d);
    }
}

__global__ void k_final(float* __restrict__ out) {
    out[0] = g_acc[0] / g_acc[1];
}

// ---------------------------------------------------------------------------
extern "C" void kernel_launch(void* const* d_in, const int* in_sizes, int n_in,
                              void* d_out, int out_size) {
    const float* z_i = (const float*)d_in[0];
    const float* z_j = (const float*)d_in[1];
    const float* w   = (const float*)d_in[2];
    float* out = (float*)d_out;

    cudaFuncSetAttribute(k_sim, cudaFuncAttributeMaxDynamicSharedMemorySize, SM_TOTAL);

    k_normalize<<<NROWS, 256>>>(z_i, z_j);
    k_sim<<<128, 256, SM_TOTAL>>>();
    k_loss<<<NHALF * 32 / 256, 256>>>(w);
    k_final<<<1, 1>>>(out);
}

// round 8
// speedup vs baseline: 1.0343x; 1.0343x over previous
#include <cuda_runtime.h>
#include <cuda_fp16.h>
#include <cstdint>
#include <math.h>

#define NHALF 4096
#define NROWS 8192
#define D 256

#define BM 256                       // CTA tile rows
#define BN 128                       // CTA tile cols
#define CSPLIT 4
#define NT 16                        // col tiles per CTA (8192/4/128)
#define NSTAGE 32                    // 16 tiles x 2 K-halves

// ---------------- device globals (no allocs allowed) ----------------
__device__ __align__(16) float  g_zn[NROWS * D];   // fp32 rows (pos dot)
__device__ __align__(16) __half g_zh[NROWS * D];   // fp16 rows (MMA)
__device__ float g_denom[NROWS];
__device__ float g_acc[2];
__device__ unsigned int g_ticket;

// ---------------- PTX helpers (arch-portable sm_80+ forms only) ----------
__device__ __forceinline__ uint32_t smem_u32(const void* p) {
    uint32_t a;
    asm("{ .reg .u64 t; cvta.to.shared.u64 t, %1; cvt.u32.u64 %0, t; }" : "=r"(a) : "l"(p));
    return a;
}
#define CPASYNC16(dst, src) \
    asm volatile("cp.async.cg.shared.global [%0], [%1], 16;" :: "r"(dst), "l"(src))
#define CPCOMMIT() asm volatile("cp.async.commit_group;" ::: "memory")
#define CPWAIT(n)  asm volatile("cp.async.wait_group %0;" :: "n"(n) : "memory")

#define LDSM4(r0, r1, r2, r3, a) \
    asm volatile("ldmatrix.sync.aligned.m8n8.x4.shared.b16 {%0,%1,%2,%3},[%4];" \
        : "=r"(r0), "=r"(r1), "=r"(r2), "=r"(r3) : "r"(a))

// fp16-accumulate HMMA (validated rel_err 0.0 in R5)
#define MMA16816H(d, a, b) \
    asm volatile("mma.sync.aligned.m16n8k16.row.col.f16.f16.f16.f16 " \
        "{%0,%1},{%2,%3,%4,%5},{%6,%7},{%0,%1};" \
        : "+r"((d)[0]), "+r"((d)[1]) \
        : "r"((a)[0]), "r"((a)[1]), "r"((a)[2]), "r"((a)[3]), "r"((b)[0]), "r"((b)[1]))

__device__ __forceinline__ float ex2f(float x) {
    float y;
    asm("ex2.approx.f32 %0, %1;" : "=f"(y) : "f"(x));
    return y;
}

// ---------------------------------------------------------------------------
// K1: normalize rows of concat(z_i,z_j): fp32 + fp16 copies; zero accumulators.
// ---------------------------------------------------------------------------
__global__ void k_normalize(const float* __restrict__ z_i,
                            const float* __restrict__ z_j) {
    int row = blockIdx.x;
    int t = threadIdx.x;
    const float* src = (row < NHALF) ? (z_i + (size_t)row * D)
                                     : (z_j + (size_t)(row - NHALF) * D);
    float v = src[t];
    float ss = v * v;
#pragma unroll
    for (int o = 16; o; o >>= 1) ss += __shfl_xor_sync(0xffffffffu, ss, o);
    __shared__ float sh[8];
    if ((t & 31) == 0) sh[t >> 5] = ss;
    __syncthreads();
    float tot = 0.f;
#pragma unroll
    for (int i = 0; i < 8; i++) tot += sh[i];
    float norm = fmaxf(sqrtf(tot), 1e-8f);
    float zn = v / norm;
    g_zn[(size_t)row * D + t] = zn;
    g_zh[(size_t)row * D + t] = __float2half(zn);
    if (t == 0) {
        g_denom[row] = 0.f;
        if (row == 0) { g_acc[0] = 0.f; g_acc[1] = 0.f; g_ticket = 0u; }
    }
}

// SMEM: A 256x512B = 128KB, then 3 B-stage buffers of 32KB (128 rows x 256B)
#define SM_B       131072
#define SM_BSTRIDE 32768
#define SM_TOTAL   (131072 + 3 * 32768)   // 224 KB

// ---------------------------------------------------------------------------
// K2: HMMA sim GEMM, 256x128 CTA tile, 8 warps of 64x64 (square warp tiles
// -> 16B/output LDSM traffic vs 24 before). B streamed as 32KB K-half stages
// through a 3-buffer cp.async ring. fp16 accumulators.
// ---------------------------------------------------------------------------
__global__ void __launch_bounds__(256) k_sim() {
    extern __shared__ char smem[];
    const int tid = threadIdx.x;
    const int wid = tid >> 5, lane = tid & 31;
    const int row0 = blockIdx.x * BM;
    const int colbase = blockIdx.y * (NROWS / CSPLIT);
    const int warp_row = (wid & 3) * 64;
    const int warp_col = (wid >> 2) * 64;

    const uint32_t sbA = smem_u32(smem);

    // ---- prologue: A (group 0, with B stage 0), B stages 1,2 ----
    {   // A: 256 rows x 512B, XOR-swizzled 16B chunks
        const char* aptr = (const char*)(g_zh + (size_t)row0 * D);
#pragma unroll
        for (int i = 0; i < 32; i++) {
            int c = tid + i * 256;         // 0..8191
            int r = c >> 5, cc = c & 31;
            CPASYNC16(sbA + r * 512 + ((cc ^ (r & 7)) << 4), aptr + (size_t)c * 16);
        }
    }
    auto load_stage = [&](int stage) {
        const int ct = stage >> 1, h = stage & 1;
        const uint32_t buf = sbA + SM_B + (stage % 3) * SM_BSTRIDE;
        const char* gbase = (const char*)g_zh
                          + (size_t)(colbase + ct * BN) * 512 + h * 256;
#pragma unroll
        for (int i = 0; i < 8; i++) {
            int c = tid + i * 256;         // 0..2047
            int n = c >> 4, cc = c & 15;
            CPASYNC16(buf + n * 256 + ((cc ^ (n & 7)) << 4),
                      gbase + (size_t)n * 512 + cc * 16);
        }
    };
    load_stage(0); CPCOMMIT();
    load_stage(1); CPCOMMIT();
    load_stage(2); CPCOMMIT();

    // ---- fragment address precompute ----
    uint32_t baseA[4]; int swA[4];
    const int hiA = lane >> 4;
#pragma unroll
    for (int mi = 0; mi < 4; mi++) {
        int rA = warp_row + mi * 16 + (lane & 15);
        baseA[mi] = sbA + rA * 512;
        swA[mi] = rA & 7;
    }
    uint32_t relB[4]; int swB[4];
    const int hiB = (lane >> 3) & 1;
#pragma unroll
    for (int np = 0; np < 4; np++) {
        int nB = warp_col + np * 16 + (lane & 7) + ((lane & 16) >> 1);
        relB[np] = nB * 256;               // 256B rows in stage buffer
        swB[np] = nB & 7;
    }

    const int gr0 = row0 + warp_row + (lane >> 2);     // global row of elt0
    const int lcw = warp_col + 2 * (lane & 3);         // local col of elt0
    const float K2E = 2.8853900817779268f;             // exp(2s)=2^(s*K2E)

    uint32_t acc[4][8][2];                 // fp16x2 accumulators (64x64/thread-tile)
    float rsum[4][2];
#pragma unroll
    for (int mi = 0; mi < 4; mi++) { rsum[mi][0] = 0.f; rsum[mi][1] = 0.f; }

#pragma unroll 1
    for (int st = 0; st < NSTAGE; st++) {
        const int ct = st >> 1, h = st & 1;
        // wait for stage st (groups complete in order)
        if (st < 30) CPWAIT(2); else if (st == 30) CPWAIT(1); else CPWAIT(0);
        __syncthreads();

        if (h == 0) {
#pragma unroll
            for (int mi = 0; mi < 4; mi++)
#pragma unroll
                for (int ni = 0; ni < 8; ni++) {
                    acc[mi][ni][0] = 0u; acc[mi][ni][1] = 0u;
                }
        }

        const uint32_t buf = sbA + SM_B + (st % 3) * SM_BSTRIDE;
#pragma unroll
        for (int sp = 0; sp < 8; sp++) {
            const int sg = h * 8 + sp;     // global k-step for A
            uint32_t af[4][4];
#pragma unroll
            for (int mi = 0; mi < 4; mi++)
                LDSM4(af[mi][0], af[mi][1], af[mi][2], af[mi][3],
                      baseA[mi] + (((2 * sg + hiA) ^ swA[mi]) << 4));
            uint32_t bfr[8][2];
#pragma unroll
            for (int np = 0; np < 4; np++) {
                uint32_t t0, t1, t2, t3;
                LDSM4(t0, t1, t2, t3,
                      buf + relB[np] + (((2 * sp + hiB) ^ swB[np]) << 4));
                bfr[2 * np][0] = t0;     bfr[2 * np][1] = t1;
                bfr[2 * np + 1][0] = t2; bfr[2 * np + 1][1] = t3;
            }
#pragma unroll
            for (int mi = 0; mi < 4; mi++)
#pragma unroll
                for (int ni = 0; ni < 8; ni++)
                    MMA16816H(acc[mi][ni], af[mi], bfr[ni]);
        }
        __syncthreads();                   // all reads of buf done
        if (st + 3 < NSTAGE) { load_stage(st + 3); CPCOMMIT(); }

        if (h == 1) {
            // ---- epilogue for tile ct: exp(2*sim), mask diagonal ----
            const int gc0 = colbase + ct * BN;
            const bool diag = (gc0 == row0 || gc0 == row0 + 128);
#pragma unroll
            for (int mi = 0; mi < 4; mi++) {
#pragma unroll
                for (int ni = 0; ni < 8; ni++) {
                    float2 f01 = __half22float2(*(__half2*)&acc[mi][ni][0]);
                    float2 f23 = __half22float2(*(__half2*)&acc[mi][ni][1]);
                    float e0 = ex2f(f01.x * K2E);
                    float e1 = ex2f(f01.y * K2E);
                    float e2 = ex2f(f23.x * K2E);
                    float e3 = ex2f(f23.y * K2E);
                    if (diag) {
                        int gr = gr0 + mi * 16;
                        int gc = gc0 + lcw + ni * 8;
                        if (gc == gr) e0 = 0.f;
                        if (gc + 1 == gr) e1 = 0.f;
                        if (gc == gr + 8) e2 = 0.f;
                        if (gc + 1 == gr + 8) e3 = 0.f;
                    }
                    rsum[mi][0] += e0 + e1;
                    rsum[mi][1] += e2 + e3;
                }
            }
        }
    }

    // ---- row reduction: shfl within warp, pair col-warps via smem ----
    float* sred = (float*)smem;            // A area reusable now
    __syncthreads();
#pragma unroll
    for (int mi = 0; mi < 4; mi++)
#pragma unroll
        for (int hh = 0; hh < 2; hh++) {
            float v = rsum[mi][hh];
            v += __shfl_xor_sync(0xffffffffu, v, 1);
            v += __shfl_xor_sync(0xffffffffu, v, 2);
            if ((lane & 3) == 0 && (wid >> 2) == 1)
                sred[warp_row + mi * 16 + hh * 8 + (lane >> 2)] = v;
            rsum[mi][hh] = v;
        }
    __syncthreads();
    if ((wid >> 2) == 0 && (lane & 3) == 0) {
#pragma unroll
        for (int mi = 0; mi < 4; mi++)
#pragma unroll
            for (int hh = 0; hh < 2; hh++) {
                int lr = warp_row + mi * 16 + hh * 8 + (lane >> 2);
                atomicAdd(&g_denom[row0 + lr], rsum[mi][hh] + sred[lr]);
            }
    }
}

// ---------------------------------------------------------------------------
// K3: fused positives + weighted loss + final division (atomic ticket).
// One warp per pair i (fp32 dot). 512 blocks; last block writes out.
// ---------------------------------------------------------------------------
#define LOSS_BLOCKS (NHALF * 32 / 256)

__global__ void k_loss(const float* __restrict__ w, float* __restrict__ out) {
    int gw = (blockIdx.x * blockDim.x + threadIdx.x) >> 5;   // pair id
    int lane = threadIdx.x & 31;
    const float4* a = (const float4*)(g_zn + (size_t)gw * D);
    const float4* b = (const float4*)(g_zn + (size_t)(gw + NHALF) * D);
    float s = 0.f;
#pragma unroll
    for (int p = 0; p < 2; p++) {
        float4 x = a[lane + p * 32];
        float4 y = b[lane + p * 32];
        s += x.x * y.x + x.y * y.y + x.z * y.z + x.w * y.w;
    }
#pragma unroll
    for (int o = 16; o; o >>= 1) s += __shfl_xor_sync(0xffffffffu, s, o);

    __shared__ float s_num[8], s_den[8];
    int wrp = threadIdx.x >> 5;
    if (lane == 0) {
        float wi = w[gw];
        s_num[wrp] = wi * (logf(g_denom[gw]) + logf(g_denom[gw + NHALF]) - 4.0f * s);
        s_den[wrp] = 2.0f * wi;
    }
    __syncthreads();
    if (threadIdx.x == 0) {
        float n = 0.f, d = 0.f;
#pragma unroll
        for (int j = 0; j < 8; j++) { n += s_num[j]; d += s_den[j]; }
        atomicAdd(&g_acc[0], n);
        atomicAdd(&g_acc[1], d);
        __threadfence();
        unsigned int t = atomicAdd(&g_ticket, 1u);
        if (t == LOSS_BLOCKS - 1) {
            volatile float* va = g_acc;
            out[0] = va[0] / va[1];
        }
    }
}

// ---------------------------------------------------------------------------
extern "C" void kernel_launch(void* const* d_in, const int* in_sizes, int n_in,
                              void* d_out, int out_size) {
    const float* z_i = (const float*)d_in[0];
    const float* z_j = (const float*)d_in[1];
    const float* w   = (const float*)d_in[2];
    float* out = (float*)d_out;

    cudaFuncSetAttribute(k_sim, cudaFuncAttributeMaxDynamicSharedMemorySize, SM_TOTAL);

    k_normalize<<<NROWS, 256>>>(z_i, z_j);
    k_sim<<<dim3(NROWS / BM, CSPLIT), 256, SM_TOTAL>>>();
    k_loss<<<LOSS_BLOCKS, 256>>>(w, out);
}